// round 7
// baseline (speedup 1.0000x reference)
#include <cuda_runtime.h>
#include <math.h>
#include <stdint.h>

#define Bv    8
#define Tv    4096
#define DIN   64
#define DRES  1024
#define NCTA  128
#define NTH   512     // 16 warps: 4 k-quarter groups x (2 row-grp x 2 batch-half)
#define NQ    4
#define CTAS_PER_Q (NCTA / NQ)

// h staging: [buf][batch-half][k][4 batches]
__device__ float g_hbuf[2][2][DRES][4];
// per-(quarter, sub(rg,bg), step) counters — addresses rotate every step
__device__ int   g_flags[NQ * 4 * Tv];

__device__ __forceinline__ void barn(int id, int cnt) {
    asm volatile("bar.sync %0, %1;" :: "r"(id), "r"(cnt) : "memory");
}
__device__ __forceinline__ void bar_arrive(int id, int cnt) {
    asm volatile("bar.arrive %0, %1;" :: "r"(id), "r"(cnt) : "memory");
}
__device__ __forceinline__ int ld_acq(const int* p) {
    int v;
    asm volatile("ld.global.acquire.gpu.b32 %0, [%1];" : "=r"(v) : "l"(p) : "memory");
    return v;
}
__device__ __forceinline__ void red_release_add(int* p, int v) {
    asm volatile("red.release.gpu.global.add.s32 [%0], %1;" :: "l"(p), "r"(v) : "memory");
}
__device__ __forceinline__ uint64_t pack2(float lo, float hi) {
    uint64_t r;
    asm("mov.b64 %0, {%1, %2};" : "=l"(r) : "f"(lo), "f"(hi));
    return r;
}
__device__ __forceinline__ void unpack2(float& lo, float& hi, uint64_t v) {
    asm("mov.b64 {%0, %1}, %2;" : "=f"(lo), "=f"(hi) : "l"(v));
}
__device__ __forceinline__ void fma2(uint64_t& d, uint64_t a, uint64_t b) {
    asm("fma.rn.f32x2 %0, %1, %2, %0;" : "+l"(d) : "l"(a), "l"(b));
}
__device__ __forceinline__ float fast_tanh(float x) {
    float e = __expf(2.0f * x);
    return 1.0f - __fdividef(2.0f, e + 1.0f);
}

__global__ void __launch_bounds__(NTH, 1) esn_kernel(
    const float* __restrict__ u,      // [B, T, DIN]
    const float* __restrict__ w_in,   // [DRES, DIN]
    const float* __restrict__ w,      // [DRES, DRES]
    const float* __restrict__ w_bias, // [DRES]
    float* __restrict__ out)          // [B, T, DRES]
{
    __shared__ float red[2][16][16];  // double-buffered reduce scratch

    const int tid  = threadIdx.x;
    const int wrp  = tid >> 5;
    const int lane = tid & 31;
    const int q    = wrp >> 2;        // k-quarter group 0..3
    const int wq   = wrp & 3;         // sub = rg*2+bg  (also SMSP index)
    const int rg   = wq >> 1;
    const int bg   = wq & 1;          // batch half (hbuf plane)
    const int r0   = rg * 4;
    const int b0   = bg * 4;
    const int cta  = blockIdx.x;
    const int r_base = cta * 8;
    const int myq  = cta >> 5;        // quarter this CTA produces into
    const int kq   = q * 256 + lane;  // base k (m=0)

    // ---- W as row-paired f32x2 in registers for all steps ----
    uint64_t Wp[8][2];
    #pragma unroll
    for (int m = 0; m < 8; ++m)
        #pragma unroll
        for (int rp = 0; rp < 2; ++rp)
            Wp[m][rp] = pack2(
                w[(size_t)(r_base + r0 + 2*rp    ) * DRES + kq + m*32],
                w[(size_t)(r_base + r0 + 2*rp + 1) * DRES + kq + m*32]);

    float2 winreg[4];
    if (q == 3) {
        #pragma unroll
        for (int rr = 0; rr < 4; ++rr)
            winreg[rr] = *(const float2*)(w_in + (r_base + r0 + rr) * DIN + lane * 2);
    }

    // ---- distributed-epilogue constants (q==0 warps, lanes 0..15) ----
    float biasr = 0.f;
    size_t ob = 0;
    if (q == 0 && lane < 16) {
        int rl  = rg * 4 + (lane >> 2);
        int bbg = bg * 4 + (lane & 3);
        biasr = w_bias[r_base + rl];
        ob    = (size_t)bbg * Tv * DRES + r_base + rl;
    }

    // post-tree-reduce value index owned by this (even) lane
    const int jred = ((lane >> 4) & 1) * 8 + ((lane >> 3) & 1) * 4
                   + ((lane >> 2) & 1) * 2 + ((lane >> 1) & 1);

    for (int t = 0; t < Tv; ++t) {
        // ---- input projection folded into acc BEFORE the flag wait ----
        uint64_t acc[2][4];
        if (q == 3) {
            float2 uv[4];
            #pragma unroll
            for (int bb = 0; bb < 4; ++bb)
                uv[bb] = __ldcg((const float2*)(u + ((size_t)(b0 + bb) * Tv + t) * DIN
                                                  + lane * 2));
            float s16[16];
            #pragma unroll
            for (int rr = 0; rr < 4; ++rr)
                #pragma unroll
                for (int bb = 0; bb < 4; ++bb)
                    s16[rr * 4 + bb] = fmaf(winreg[rr].y, uv[bb].y,
                                            winreg[rr].x * uv[bb].x);
            #pragma unroll
            for (int rp = 0; rp < 2; ++rp)
                #pragma unroll
                for (int bb = 0; bb < 4; ++bb)
                    acc[rp][bb] = pack2(s16[(2*rp)*4 + bb], s16[(2*rp+1)*4 + bb]);
        } else {
            #pragma unroll
            for (int rp = 0; rp < 2; ++rp)
                #pragma unroll
                for (int bb = 0; bb < 4; ++bb) acc[rp][bb] = 0ull;
        }

        if (t > 0) {
            if (wq == q) {                         // poll warp (spread over SMSPs)
                if (lane < 4) {
                    const int* fp = &g_flags[(q * 4 + lane) * Tv + (t - 1)];
                    while (ld_acq(fp) < CTAS_PER_Q) { }
                }
                __syncwarp();
            }
            barn(q + 1, 128);                      // propagate acquire to group

            // H quarter direct to registers (plane = batch half)
            const float* hb = &g_hbuf[(t - 1) & 1][bg][0][0];
            float4 h4[8];
            #pragma unroll
            for (int m = 0; m < 8; ++m)
                h4[m] = __ldcg((const float4*)(hb + (size_t)(kq + m * 32) * 4));

            #pragma unroll
            for (int m = 0; m < 8; ++m) {
                const float* hm = (const float*)&h4[m];
                #pragma unroll
                for (int b = 0; b < 4; ++b) {
                    uint64_t hr = pack2(hm[b], hm[b]);
                    fma2(acc[0][b], Wp[m][0], hr);
                    fma2(acc[1][b], Wp[m][1], hr);
                }
            }
        }

        float acc16[16];
        #pragma unroll
        for (int rp = 0; rp < 2; ++rp)
            #pragma unroll
            for (int b = 0; b < 4; ++b)
                unpack2(acc16[(2 * rp) * 4 + b], acc16[(2 * rp + 1) * 4 + b], acc[rp][b]);

        // ---- register-halving tree reduce (31 SHFL) ----
        #pragma unroll
        for (int i = 0; i < 16; ++i) acc16[i] += __shfl_xor_sync(~0u, acc16[i], 16);
        float v8[8];
        #pragma unroll
        for (int i = 0; i < 8; ++i) v8[i] = (lane & 16) ? acc16[i + 8] : acc16[i];
        #pragma unroll
        for (int i = 0; i < 8; ++i) v8[i] += __shfl_xor_sync(~0u, v8[i], 8);
        float v4[4];
        #pragma unroll
        for (int i = 0; i < 4; ++i) v4[i] = (lane & 8) ? v8[i + 4] : v8[i];
        #pragma unroll
        for (int i = 0; i < 4; ++i) v4[i] += __shfl_xor_sync(~0u, v4[i], 4);
        float v2[2];
        #pragma unroll
        for (int i = 0; i < 2; ++i) v2[i] = (lane & 4) ? v4[i + 2] : v4[i];
        #pragma unroll
        for (int i = 0; i < 2; ++i) v2[i] += __shfl_xor_sync(~0u, v2[i], 2);
        float v1 = (lane & 2) ? v2[1] : v2[0];
        v1 += __shfl_xor_sync(~0u, v1, 1);

        float* redt = &red[t & 1][0][0];
        if (!(lane & 1)) redt[wrp * 16 + jred] = v1;

        // ---- foursome handoff: (rg,bg)-peers arrive, q0 warp finalizes ----
        if (q != 0) {
            bar_arrive(8 + wq, 128);
            continue;                              // straight to next step
        }
        barn(8 + wq, 128);                         // wait for 3 k-quarter peers

        // ---- distributed epilogue: 16 lanes, one output each ----
        float s = 0.f;
        if (lane < 16) {
            s = redt[wq * 16 + lane]      + redt[(4 + wq) * 16 + lane]
              + redt[(8 + wq) * 16 + lane] + redt[(12 + wq) * 16 + lane];
            s = fast_tanh(s + biasr);
            *(&g_hbuf[t & 1][bg][r_base + rg * 4][0] + lane) = s;   // 64B coalesced
        }
        __syncwarp();                              // hbuf stores ordered
        if (lane == 0)
            red_release_add(&g_flags[(myq * 4 + wq) * Tv + t], 1);
        if (lane < 16)
            out[ob + (size_t)t * DRES] = s;        // off the critical path
    }
}

extern "C" void kernel_launch(void* const* d_in, const int* in_sizes, int n_in,
                              void* d_out, int out_size) {
    const float* u      = (const float*)d_in[0];
    const float* w_in   = (const float*)d_in[1];
    const float* w      = (const float*)d_in[2];
    const float* w_bias = (const float*)d_in[3];
    float* out = (float*)d_out;

    void* flagsPtr = nullptr;
    cudaGetSymbolAddress(&flagsPtr, g_flags);
    cudaMemsetAsync(flagsPtr, 0, NQ * 4 * Tv * sizeof(int), 0);

    esn_kernel<<<NCTA, NTH>>>(u, w_in, w, w_bias, out);
}

// round 8
// speedup vs baseline: 1.2351x; 1.2351x over previous
#include <cuda_runtime.h>
#include <math.h>
#include <stdint.h>

#define Bv    8
#define Tv    4096
#define DIN   64
#define DRES  1024
#define NCTA  128
#define NTH   512     // 16 warps: 4 k-quarter groups x (2 row-grp x 2 batch-half)
#define NQ    4
#define CTAS_PER_Q (NCTA / NQ)

// h staging: [buf][batch-half][k][4 batches]
__device__ float g_hbuf[2][2][DRES][4];
// per-(quarter,step) completion counters — address rotates every step
__device__ int   g_flags[NQ * Tv];

__device__ __forceinline__ void barn(int id, int cnt) {
    asm volatile("bar.sync %0, %1;" :: "r"(id), "r"(cnt) : "memory");
}
__device__ __forceinline__ void bar_arrive(int id, int cnt) {
    asm volatile("bar.arrive %0, %1;" :: "r"(id), "r"(cnt) : "memory");
}
__device__ __forceinline__ int ld_acq(const int* p) {
    int v;
    asm volatile("ld.global.acquire.gpu.b32 %0, [%1];" : "=r"(v) : "l"(p) : "memory");
    return v;
}
__device__ __forceinline__ void red_release_add(int* p, int v) {
    asm volatile("red.release.gpu.global.add.s32 [%0], %1;" :: "l"(p), "r"(v) : "memory");
}
__device__ __forceinline__ uint64_t pack2(float lo, float hi) {
    uint64_t r;
    asm("mov.b64 %0, {%1, %2};" : "=l"(r) : "f"(lo), "f"(hi));
    return r;
}
__device__ __forceinline__ void unpack2(float& lo, float& hi, uint64_t v) {
    asm("mov.b64 {%0, %1}, %2;" : "=f"(lo), "=f"(hi) : "l"(v));
}
__device__ __forceinline__ void fma2(uint64_t& d, uint64_t a, uint64_t b) {
    asm("fma.rn.f32x2 %0, %1, %2, %0;" : "+l"(d) : "l"(a), "l"(b));
}
__device__ __forceinline__ float fast_tanh(float x) {
    float e = __expf(2.0f * x);
    return 1.0f - __fdividef(2.0f, e + 1.0f);
}

__global__ void __launch_bounds__(NTH, 1) esn_kernel(
    const float* __restrict__ u,      // [B, T, DIN]
    const float* __restrict__ w_in,   // [DRES, DIN]
    const float* __restrict__ w,      // [DRES, DRES]
    const float* __restrict__ w_bias, // [DRES]
    float* __restrict__ out)          // [B, T, DRES]
{
    __shared__ float red[2][256];     // double-buffered reduce scratch

    const int tid  = threadIdx.x;
    const int wrp  = tid >> 5;
    const int lane = tid & 31;
    const int q    = wrp >> 2;        // k-quarter group 0..3
    const int wq   = wrp & 3;         // sub = rg*2+bg (also SMSP index)
    const int rg   = wq >> 1;
    const int bg   = wq & 1;          // batch half (hbuf plane)
    const int r0   = rg * 4;
    const int b0   = bg * 4;
    const int cta  = blockIdx.x;
    const int r_base = cta * 8;
    const int myq  = cta >> 5;        // quarter this CTA produces into
    const int kq   = q * 256 + lane;  // base k (m=0)
    const bool is_epi = (wrp < 2);    // epilogue warps (q=0, wq=0/1)

    // ---- W as row-paired f32x2 in registers for all steps ----
    uint64_t Wp[8][2];
    #pragma unroll
    for (int m = 0; m < 8; ++m)
        #pragma unroll
        for (int rp = 0; rp < 2; ++rp)
            Wp[m][rp] = pack2(
                w[(size_t)(r_base + r0 + 2*rp    ) * DRES + kq + m*32],
                w[(size_t)(r_base + r0 + 2*rp + 1) * DRES + kq + m*32]);

    float2 winreg[4];
    if (q == 3) {
        #pragma unroll
        for (int rr = 0; rr < 4; ++rr)
            winreg[rr] = *(const float2*)(w_in + (r_base + r0 + rr) * DIN + lane * 2);
    }

    // ---- epilogue constants (tid < 64, one output each) ----
    float biasr = 0.f;
    int hoff = 0;
    size_t ob = 0;
    if (tid < 64) {
        int tile = tid >> 4, idx = tid & 15;
        int rl = (tile >> 1) * 4 + (idx >> 2);
        int bb = (tile & 1) * 4 + (idx & 3);
        biasr = w_bias[r_base + rl];
        hoff  = ((bb >> 2) * DRES + r_base + rl) * 4 + (bb & 3);
        ob    = (size_t)bb * Tv * DRES + r_base + rl;
    }

    // post-tree-reduce value index owned by this (even) lane
    const int jred = ((lane >> 4) & 1) * 8 + ((lane >> 3) & 1) * 4
                   + ((lane >> 2) & 1) * 2 + ((lane >> 1) & 1);

    for (int t = 0; t < Tv; ++t) {
        // ---- input projection folded into acc BEFORE the flag wait ----
        uint64_t acc[2][4];
        if (q == 3) {
            float2 uv[4];
            #pragma unroll
            for (int bb = 0; bb < 4; ++bb)
                uv[bb] = __ldcg((const float2*)(u + ((size_t)(b0 + bb) * Tv + t) * DIN
                                                  + lane * 2));
            float s16[16];
            #pragma unroll
            for (int rr = 0; rr < 4; ++rr)
                #pragma unroll
                for (int bb = 0; bb < 4; ++bb)
                    s16[rr * 4 + bb] = fmaf(winreg[rr].y, uv[bb].y,
                                            winreg[rr].x * uv[bb].x);
            #pragma unroll
            for (int rp = 0; rp < 2; ++rp)
                #pragma unroll
                for (int bb = 0; bb < 4; ++bb)
                    acc[rp][bb] = pack2(s16[(2*rp)*4 + bb], s16[(2*rp+1)*4 + bb]);
        } else {
            #pragma unroll
            for (int rp = 0; rp < 2; ++rp)
                #pragma unroll
                for (int bb = 0; bb < 4; ++bb) acc[rp][bb] = 0ull;
        }

        if (t > 0) {
            if (wq == q) {                         // poll warp, one per SMSP
                const int* fp = &g_flags[q * Tv + (t - 1)];
                while (ld_acq(fp) < CTAS_PER_Q) { }
            }
            barn(q + 1, 128);                      // propagate acquire to group

            // H quarter direct to registers (plane = batch half, full sectors)
            const float* hb = &g_hbuf[(t - 1) & 1][bg][0][0];
            float4 h4[8];
            #pragma unroll
            for (int m = 0; m < 8; ++m)
                h4[m] = __ldcg((const float4*)(hb + (size_t)(kq + m * 32) * 4));

            #pragma unroll
            for (int m = 0; m < 8; ++m) {
                const float* hm = (const float*)&h4[m];
                #pragma unroll
                for (int b = 0; b < 4; ++b) {
                    uint64_t hr = pack2(hm[b], hm[b]);
                    fma2(acc[0][b], Wp[m][0], hr);
                    fma2(acc[1][b], Wp[m][1], hr);
                }
            }
        }

        float acc16[16];
        #pragma unroll
        for (int rp = 0; rp < 2; ++rp)
            #pragma unroll
            for (int b = 0; b < 4; ++b)
                unpack2(acc16[(2 * rp) * 4 + b], acc16[(2 * rp + 1) * 4 + b], acc[rp][b]);

        // ---- register-halving tree reduce (31 SHFL) ----
        #pragma unroll
        for (int i = 0; i < 16; ++i) acc16[i] += __shfl_xor_sync(~0u, acc16[i], 16);
        float v8[8];
        #pragma unroll
        for (int i = 0; i < 8; ++i) v8[i] = (lane & 16) ? acc16[i + 8] : acc16[i];
        #pragma unroll
        for (int i = 0; i < 8; ++i) v8[i] += __shfl_xor_sync(~0u, v8[i], 8);
        float v4[4];
        #pragma unroll
        for (int i = 0; i < 4; ++i) v4[i] = (lane & 8) ? v8[i + 4] : v8[i];
        #pragma unroll
        for (int i = 0; i < 4; ++i) v4[i] += __shfl_xor_sync(~0u, v4[i], 4);
        float v2[2];
        #pragma unroll
        for (int i = 0; i < 2; ++i) v2[i] = (lane & 4) ? v4[i + 2] : v4[i];
        #pragma unroll
        for (int i = 0; i < 2; ++i) v2[i] += __shfl_xor_sync(~0u, v2[i], 2);
        float v1 = (lane & 2) ? v2[1] : v2[0];
        v1 += __shfl_xor_sync(~0u, v1, 1);

        float* redt = &red[t & 1][0];
        if (!(lane & 1)) redt[wrp * 16 + jred] = v1;

        // ---- decoupled handoff: producers arrive and run ahead ----
        if (!is_epi) {
            bar_arrive(15, NTH);
            continue;                              // straight to next step
        }
        barn(15, NTH);                             // epilogue warps wait for all STS

        // ---- epilogue: 64 threads, one output each ----
        if (tid < 64) {
            float s = redt[tid] + redt[64 + tid]
                    + redt[128 + tid] + redt[192 + tid];
            s = fast_tanh(s + biasr);
            (&g_hbuf[t & 1][0][0][0])[hoff] = s;
            barn(9, 64);                           // hbuf stores ordered before flag
            if (tid == 0)
                red_release_add(&g_flags[myq * Tv + t], 1);
            out[ob + (size_t)t * DRES] = s;        // off the critical path
        }
    }
}

extern "C" void kernel_launch(void* const* d_in, const int* in_sizes, int n_in,
                              void* d_out, int out_size) {
    const float* u      = (const float*)d_in[0];
    const float* w_in   = (const float*)d_in[1];
    const float* w      = (const float*)d_in[2];
    const float* w_bias = (const float*)d_in[3];
    float* out = (float*)d_out;

    void* flagsPtr = nullptr;
    cudaGetSymbolAddress(&flagsPtr, g_flags);
    cudaMemsetAsync(flagsPtr, 0, NQ * Tv * sizeof(int), 0);

    esn_kernel<<<NCTA, NTH>>>(u, w_in, w, w_bias, out);
}